// round 1
// baseline (speedup 1.0000x reference)
#include <cuda_runtime.h>
#include <math.h>

// ---------------------------------------------------------------------------
// StateModelEncoder: RGCN + TAG (game graph) -> gx ; then GraphConv/SAGE/TAG/SAGE
// chain on state graph -> linear head.
//
// Strategy:
//  * All aggregations are linear => aggregate-then-transform (RGCN/TAG-game run
//    in DIN=5 space; SAGE/TAG-state in H=64 space).
//  * Shared aggregations computed once (ei_in mean used by conv4 & conv42;
//    ei_h gather fused for graph_conv + conv32; deg over ei_ss shared by
//    TAG-state norm and conv5 mean).
//  * Edge passes: warp-per-edge (64-dim) / thread-per-edge (5-dim), atomicAdd
//    scatter. Feature tables fit in L2.
// ---------------------------------------------------------------------------

static const int NVx  = 100000;   // game nodes
static const int NSx  = 50000;    // state nodes
static const int Hx   = 64;
static const int DINx = 5;

// ------------------------- scratch (device globals) ------------------------
__device__ float g_racc[NVx * 15];          // RGCN per-relation 5-dim sums
__device__ float g_rcnt[NVx * 3];           // RGCN per-relation counts
__device__ float g_dinv_v[NVx];             // TAG-game 1/sqrt(deg)
__device__ float g_hv[3][NVx * 5];          // TAG-game hop features
__device__ float g_gx[(size_t)NVx * 64];    // fused game embedding
__device__ float g_accw[(size_t)NSx * 64];  // ei_h weighted sum of gx
__device__ float g_accu[(size_t)NSx * 64];  // ei_h plain sum of gx
__device__ float g_cnt_h[NSx];
__device__ float g_accin[(size_t)NSx * 64]; // ei_in sum of gx
__device__ float g_cnt_in[NSx];
__device__ float g_sxA[(size_t)NSx * 64];
__device__ float g_sxB[(size_t)NSx * 64];
__device__ float g_hs[3][(size_t)NSx * 64]; // TAG-state hop features
__device__ float g_accs5[(size_t)NSx * 64]; // ei_ss sum of sx6 (conv5)
__device__ float g_deg_s[NSx];              // deg over ei_ss (= conv5 count)
__device__ float g_dinv_s[NSx];

// ------------------------------- kernels -----------------------------------

__global__ void k_zero_all() {
    size_t i0 = (size_t)blockIdx.x * blockDim.x + threadIdx.x;
    size_t st = (size_t)gridDim.x * blockDim.x;
    for (size_t i = i0; i < (size_t)NVx * 15; i += st) g_racc[i] = 0.f;
    for (size_t i = i0; i < (size_t)NVx * 3;  i += st) g_rcnt[i] = 0.f;
    for (size_t i = i0; i < (size_t)NVx * 5;  i += st) {
        g_hv[0][i] = 0.f; g_hv[1][i] = 0.f; g_hv[2][i] = 0.f;
    }
    for (size_t i = i0; i < (size_t)NSx * 64; i += st) {
        g_accw[i] = 0.f; g_accu[i] = 0.f; g_accin[i] = 0.f;
        g_hs[0][i] = 0.f; g_hs[1][i] = 0.f; g_hs[2][i] = 0.f;
        g_accs5[i] = 0.f;
    }
    for (size_t i = i0; i < (size_t)NSx; i += st) {
        g_cnt_h[i] = 0.f; g_cnt_in[i] = 0.f; g_deg_s[i] = 0.f;
    }
}

// RGCN edge pass: 5-dim sums per (dst, relation) + counts.
__global__ void k_rgcn_edge(const int* __restrict__ ei, const int* __restrict__ et,
                            const float* __restrict__ x, int E) {
    int e = blockIdx.x * blockDim.x + threadIdx.x;
    if (e >= E) return;
    int s = ei[e], d = ei[E + e], t = et[e];
    const float* xs = x + (size_t)s * 5;
    float* a = g_racc + (size_t)d * 15 + t * 5;
#pragma unroll
    for (int i = 0; i < 5; i++) atomicAdd(a + i, xs[i]);
    atomicAdd(g_rcnt + (size_t)d * 3 + t, 1.0f);
}

__global__ void k_dinv_v() {
    int v = blockIdx.x * blockDim.x + threadIdx.x;
    if (v >= NVx) return;
    float deg = g_rcnt[3 * v] + g_rcnt[3 * v + 1] + g_rcnt[3 * v + 2];
    g_dinv_v[v] = (deg > 0.f) ? rsqrtf(deg) : 0.f;
}

// TAG-game hop: 5-dim normalized scatter.
__global__ void k_hop5(const float* __restrict__ hp, float* __restrict__ hn,
                       const int* __restrict__ ei, int E) {
    int e = blockIdx.x * blockDim.x + threadIdx.x;
    if (e >= E) return;
    int s = ei[e], d = ei[E + e];
    float nrm = g_dinv_v[s] * g_dinv_v[d];
    if (nrm == 0.f) return;
    const float* hs = hp + (size_t)s * 5;
    float* hd = hn + (size_t)d * 5;
#pragma unroll
    for (int i = 0; i < 5; i++) atomicAdd(hd + i, nrm * hs[i]);
}

// gx[v][c] = b1+b12 + x@(W1_root+W12[0]) + sum_r (racc_r/c_r)@W1_rel[r]
//          + sum_k h_k@W12[k]
__global__ void k_gx(const float* __restrict__ x,
                     const float* __restrict__ W1_rel, const float* __restrict__ W1_root,
                     const float* __restrict__ b1,
                     const float* __restrict__ W12, const float* __restrict__ b12) {
    int t = blockIdx.x * blockDim.x + threadIdx.x;
    int v = t >> 6, c = t & 63;
    if (v >= NVx) return;
    float acc = b1[c] + b12[c];
    const float* xv = x + (size_t)v * 5;
#pragma unroll
    for (int i = 0; i < 5; i++)
        acc += xv[i] * (W1_root[i * 64 + c] + W12[i * 64 + c]);
#pragma unroll
    for (int r = 0; r < 3; r++) {
        float inv = 1.f / fmaxf(g_rcnt[v * 3 + r], 1.f);
        float sa = 0.f;
#pragma unroll
        for (int i = 0; i < 5; i++)
            sa += g_racc[v * 15 + r * 5 + i] * W1_rel[(r * 5 + i) * 64 + c];
        acc += sa * inv;
    }
#pragma unroll
    for (int k = 0; k < 3; k++) {
        const float* h = g_hv[k] + (size_t)v * 5;
#pragma unroll
        for (int i = 0; i < 5; i++)
            acc += h[i] * W12[((k + 1) * 5 + i) * 64 + c];
    }
    g_gx[(size_t)v * 64 + c] = acc;
}

// Fused ei_h pass: weighted sum (graph_conv) + plain sum + count (conv32 mean).
__global__ void k_scatter_h(const int* __restrict__ ei, const float* __restrict__ ew, int E) {
    int gt = blockIdx.x * blockDim.x + threadIdx.x;
    int w = gt >> 5, lane = gt & 31;
    if (w >= E) return;
    int s = ei[w], d = ei[E + w];
    float wt = ew[w];
    const float* f = g_gx + (size_t)s * 64;
    float a = f[lane], b = f[lane + 32];
    float* pw = g_accw + (size_t)d * 64;
    float* pu = g_accu + (size_t)d * 64;
    atomicAdd(pw + lane, wt * a);       atomicAdd(pw + lane + 32, wt * b);
    atomicAdd(pu + lane, a);            atomicAdd(pu + lane + 32, b);
    if (lane == 0) atomicAdd(g_cnt_h + d, 1.f);
}

// Generic 64-dim sum scatter (+ optional count).
__global__ void k_scatter64(const int* __restrict__ ei, const float* __restrict__ feat,
                            float* __restrict__ acc, float* __restrict__ cnt, int E) {
    int gt = blockIdx.x * blockDim.x + threadIdx.x;
    int w = gt >> 5, lane = gt & 31;
    if (w >= E) return;
    int s = ei[w], d = ei[E + w];
    const float* f = feat + (size_t)s * 64;
    float* p = acc + (size_t)d * 64;
    atomicAdd(p + lane, f[lane]);
    atomicAdd(p + lane + 32, f[lane + 32]);
    if (cnt && lane == 0) atomicAdd(cnt + d, 1.f);
}

// 64-dim sym-normalized scatter (TAG-state hop).
__global__ void k_hop64(const int* __restrict__ ei, const float* __restrict__ hp,
                        float* __restrict__ hn, int E) {
    int gt = blockIdx.x * blockDim.x + threadIdx.x;
    int w = gt >> 5, lane = gt & 31;
    if (w >= E) return;
    int s = ei[w], d = ei[E + w];
    float nrm = g_dinv_s[s] * g_dinv_s[d];
    if (nrm == 0.f) return;
    const float* f = hp + (size_t)s * 64;
    float* p = hn + (size_t)d * 64;
    atomicAdd(p + lane, nrm * f[lane]);
    atomicAdd(p + lane + 32, nrm * f[lane + 32]);
}

__global__ void k_count(const int* __restrict__ ei, float* __restrict__ cnt, int E) {
    int e = blockIdx.x * blockDim.x + threadIdx.x;
    if (e >= E) return;
    atomicAdd(cnt + ei[E + e], 1.f);
}

__global__ void k_dinv_g(const float* __restrict__ deg, float* __restrict__ dinv, int n) {
    int v = blockIdx.x * blockDim.x + threadIdx.x;
    if (v >= n) return;
    float d = deg[v];
    dinv[v] = (d > 0.f) ? rsqrtf(d) : 0.f;
}

// out = [relu]( (A[/cnt]) @ Wa + X @ Wx + b )
__global__ void k_dense(const float* __restrict__ A, const float* __restrict__ cnt,
                        const float* __restrict__ Wa,
                        const float* __restrict__ X, int dx, const float* __restrict__ Wx,
                        const float* __restrict__ b, float* __restrict__ out,
                        int n, int dorelu) {
    int t = blockIdx.x * blockDim.x + threadIdx.x;
    int v = t >> 6, c = t & 63;
    if (v >= n) return;
    float inv = cnt ? (1.f / fmaxf(cnt[v], 1.f)) : 1.f;
    const float* av = A + (size_t)v * 64;
    float sa = 0.f;
#pragma unroll
    for (int j = 0; j < 64; j++) sa += av[j] * Wa[j * 64 + c];
    float acc = b[c] + sa * inv;
    const float* xv = X + (size_t)v * dx;
    for (int j = 0; j < dx; j++) acc += xv[j] * Wx[j * 64 + c];
    if (dorelu) acc = fmaxf(acc, 0.f);
    out[(size_t)v * 64 + c] = acc;
}

// TAG-state output: relu(b2 + sx@W2[0] + h1@W2[1] + h2@W2[2] + h3@W2[3])
__global__ void k_tag_out(const float* __restrict__ sx, const float* __restrict__ W2,
                          const float* __restrict__ b2, float* __restrict__ out) {
    int t = blockIdx.x * blockDim.x + threadIdx.x;
    int v = t >> 6, c = t & 63;
    if (v >= NSx) return;
    float acc = b2[c];
    const float* s0 = sx + (size_t)v * 64;
#pragma unroll
    for (int j = 0; j < 64; j++) acc += s0[j] * W2[j * 64 + c];
#pragma unroll
    for (int k = 0; k < 3; k++) {
        const float* hk = g_hs[k] + (size_t)v * 64;
        const float* wk = W2 + (size_t)(k + 1) * 4096;
#pragma unroll
        for (int j = 0; j < 64; j++) acc += hk[j] * wk[j * 64 + c];
    }
    out[(size_t)v * 64 + c] = fmaxf(acc, 0.f);
}

__global__ void k_final(const float* __restrict__ sx, const float* __restrict__ Wl,
                        const float* __restrict__ bl, float* __restrict__ out) {
    int t = blockIdx.x * blockDim.x + threadIdx.x;
    int v = t >> 3, c = t & 7;
    if (v >= NSx) return;
    float acc = bl[c];
    const float* s0 = sx + (size_t)v * 64;
#pragma unroll
    for (int j = 0; j < 64; j++) acc += s0[j] * Wl[j * 8 + c];
    out[(size_t)v * 8 + c] = acc;
}

// ------------------------------- launch ------------------------------------

extern "C" void kernel_launch(void* const* d_in, const int* in_sizes, int n_in,
                              void* d_out, int out_size) {
    const float* game_x  = (const float*)d_in[0];
    const float* state_x = (const float*)d_in[1];
    const int*   ei_vv   = (const int*)d_in[2];
    const int*   et_vv   = (const int*)d_in[3];
    const int*   ei_h    = (const int*)d_in[4];
    const float* ew_h    = (const float*)d_in[5];
    const int*   ei_in   = (const int*)d_in[6];
    const int*   ei_ss   = (const int*)d_in[7];
    const float* W1_rel  = (const float*)d_in[8];
    const float* W1_root = (const float*)d_in[9];
    const float* b1      = (const float*)d_in[10];
    const float* W12     = (const float*)d_in[11];
    const float* b12     = (const float*)d_in[12];
    const float* W2      = (const float*)d_in[13];
    const float* b2      = (const float*)d_in[14];
    const float* W3_rel  = (const float*)d_in[15];
    const float* W3_root = (const float*)d_in[16];
    const float* b3      = (const float*)d_in[17];
    const float* W32_l   = (const float*)d_in[18];
    const float* W32_r   = (const float*)d_in[19];
    const float* b32     = (const float*)d_in[20];
    const float* W4_l    = (const float*)d_in[21];
    const float* W4_r    = (const float*)d_in[22];
    const float* b4      = (const float*)d_in[23];
    const float* W42_l   = (const float*)d_in[24];
    const float* W42_r   = (const float*)d_in[25];
    const float* b42     = (const float*)d_in[26];
    const float* W5_l    = (const float*)d_in[27];
    const float* W5_r    = (const float*)d_in[28];
    const float* b5      = (const float*)d_in[29];
    const float* Wl      = (const float*)d_in[30];
    const float* bl      = (const float*)d_in[31];
    float* out = (float*)d_out;

    int Evv = in_sizes[2] / 2;
    int Eh  = in_sizes[4] / 2;
    int Ein = in_sizes[6] / 2;
    int Ess = in_sizes[7] / 2;

    // resolve scratch addresses (host-visible)
    float *p_accw, *p_accu, *p_cnt_h, *p_accin, *p_cnt_in, *p_sxA, *p_sxB;
    float *p_hs0, *p_hs1, *p_hs2, *p_accs5, *p_deg_s, *p_dinv_s, *p_hv0, *p_hv1, *p_hv2;
    cudaGetSymbolAddress((void**)&p_accw,  g_accw);
    cudaGetSymbolAddress((void**)&p_accu,  g_accu);
    cudaGetSymbolAddress((void**)&p_cnt_h, g_cnt_h);
    cudaGetSymbolAddress((void**)&p_accin, g_accin);
    cudaGetSymbolAddress((void**)&p_cnt_in,g_cnt_in);
    cudaGetSymbolAddress((void**)&p_sxA,   g_sxA);
    cudaGetSymbolAddress((void**)&p_sxB,   g_sxB);
    cudaGetSymbolAddress((void**)&p_hs0,   g_hs);
    p_hs1 = p_hs0 + (size_t)NSx * 64;
    p_hs2 = p_hs1 + (size_t)NSx * 64;
    cudaGetSymbolAddress((void**)&p_accs5, g_accs5);
    cudaGetSymbolAddress((void**)&p_deg_s, g_deg_s);
    cudaGetSymbolAddress((void**)&p_dinv_s,g_dinv_s);
    cudaGetSymbolAddress((void**)&p_hv0,   g_hv);
    p_hv1 = p_hv0 + (size_t)NVx * 5;
    p_hv2 = p_hv1 + (size_t)NVx * 5;

    const int T = 256;
    auto nb = [](long n, int t) { return (int)((n + t - 1) / t); };

    // 0) zero accumulators
    k_zero_all<<<2048, T>>>();

    // 1) game graph: RGCN sums + counts
    k_rgcn_edge<<<nb(Evv, T), T>>>(ei_vv, et_vv, game_x, Evv);
    k_dinv_v<<<nb(NVx, T), T>>>();

    // 2) TAG-game hops (5-dim)
    k_hop5<<<nb(Evv, T), T>>>(game_x, p_hv0, ei_vv, Evv);
    k_hop5<<<nb(Evv, T), T>>>(p_hv0, p_hv1, ei_vv, Evv);
    k_hop5<<<nb(Evv, T), T>>>(p_hv1, p_hv2, ei_vv, Evv);

    // 3) fused node transform -> gx
    k_gx<<<nb((long)NVx * 64, T), T>>>(game_x, W1_rel, W1_root, b1, W12, b12);

    // 4) ei_h fused gather (weighted + plain + count)
    k_scatter_h<<<nb((long)Eh * 32, T), T>>>(ei_h, ew_h, Eh);

    // 5) graph_conv (layer2) -> sxA ; conv32 SAGE (layer3) -> sxB
    k_dense<<<nb((long)NSx * 64, T), T>>>(p_accw, nullptr, W3_rel, state_x, 5, W3_root, b3, p_sxA, NSx, 1);
    k_dense<<<nb((long)NSx * 64, T), T>>>(p_accu, p_cnt_h, W32_l, p_sxA, 64, W32_r, b32, p_sxB, NSx, 1);

    // 6) ei_in mean of gx (shared by conv4 & conv42)
    k_scatter64<<<nb((long)Ein * 32, T), T>>>(ei_in, (const float*)nullptr == nullptr ? p_accin - 0 : p_accin, p_accin, p_cnt_in, Ein); // placeholder removed below
    // (note: feat is g_gx; see corrected call)
    // -- corrected call:
    // (we cannot easily reference g_gx from host; k_scatter64 takes feat ptr)
    // resolve gx address:
    {
        float* p_gx; cudaGetSymbolAddress((void**)&p_gx, g_gx);
        // redo the ei_in scatter properly (the call above used p_accin as feat by mistake;
        // overwrite: zero accin/cnt_in then scatter from gx)
        cudaMemsetAsync(p_accin, 0, (size_t)NSx * 64 * sizeof(float), 0);
        cudaMemsetAsync(p_cnt_in, 0, (size_t)NSx * sizeof(float), 0);
        k_scatter64<<<nb((long)Ein * 32, T), T>>>(ei_in, p_gx, p_accin, p_cnt_in, Ein);

        // also fix: k_scatter_h and dense already used correct globals.
        // 7) conv4 -> sxA ; conv42 -> sxB
        k_dense<<<nb((long)NSx * 64, T), T>>>(p_accin, p_cnt_in, W4_l,  p_sxB, 64, W4_r,  b4,  p_sxA, NSx, 1);
        k_dense<<<nb((long)NSx * 64, T), T>>>(p_accin, p_cnt_in, W42_l, p_sxA, 64, W42_r, b42, p_sxB, NSx, 1);

        // 8) TAG-state on ei_ss (sx5 = sxB)
        k_count<<<nb(Ess, T), T>>>(ei_ss, p_deg_s, Ess);
        k_dinv_g<<<nb(NSx, T), T>>>(p_deg_s, p_dinv_s, NSx);
        k_hop64<<<nb((long)Ess * 32, T), T>>>(ei_ss, p_sxB, p_hs0, Ess);
        k_hop64<<<nb((long)Ess * 32, T), T>>>(ei_ss, p_hs0, p_hs1, Ess);
        k_hop64<<<nb((long)Ess * 32, T), T>>>(ei_ss, p_hs1, p_hs2, Ess);
        k_tag_out<<<nb((long)NSx * 64, T), T>>>(p_sxB, W2, b2, p_sxA);   // sx6 = sxA

        // 9) conv5 SAGE over ei_ss (count = deg_s)
        k_scatter64<<<nb((long)Ess * 32, T), T>>>(ei_ss, p_sxA, p_accs5, (float*)nullptr, Ess);
        k_dense<<<nb((long)NSx * 64, T), T>>>(p_accs5, p_deg_s, W5_l, p_sxA, 64, W5_r, b5, p_sxB, NSx, 1);

        // 10) head
        k_final<<<nb((long)NSx * 8, T), T>>>(p_sxB, Wl, bl, out);
    }
}

// round 2
// speedup vs baseline: 1.4171x; 1.4171x over previous
#include <cuda_runtime.h>
#include <math.h>

// ---------------------------------------------------------------------------
// StateModelEncoder — round 2: vector atomics (red.v4.f32), gx elimination
// via 40-dim z-space aggregation, 2-edge warp packing.
// ---------------------------------------------------------------------------

#define NVn 100000
#define NSn 50000

// ------------------------- scratch (device globals) ------------------------
__device__ __align__(16) float g_xpad[NVn * 8];        // game_x padded to 8
__device__ __align__(16) float g_racc[NVn * 24];       // [v][rel][8] rgcn sums
__device__ float g_rcnt[NVn * 4];                      // [v][rel] counts (3 used)
__device__ float g_dinv_v[NVn];
__device__ __align__(16) float g_hv[3][NVn * 8];       // TAG-game hops (padded 8)
__device__ __align__(16) float g_z[NVn * 40];          // 35-dim z, padded 40
__device__ __align__(16) float g_Wz[40 * 64];
__device__ float g_c0[64];
__device__ __align__(16) float g_WzW[4][40 * 64];      // Wz @ {W3_rel,W32_l,W4_l,W42_l}
__device__ float g_c0W[4][64];                          // c0 @ {...}
__device__ __align__(16) float g_aggw[NSn * 40];       // ei_h weighted z-sum
__device__ __align__(16) float g_aggu[NSn * 40];       // ei_h plain z-sum
__device__ float g_cnt_h[NSn];
__device__ float g_wsum_h[NSn];
__device__ __align__(16) float g_aggin[NSn * 40];      // ei_in z-sum
__device__ float g_cnt_in[NSn];
__device__ __align__(16) float g_sxA[NSn * 64];
__device__ __align__(16) float g_sxB[NSn * 64];
__device__ __align__(16) float g_hs[3][NSn * 64];      // TAG-state hops
__device__ __align__(16) float g_accs5[NSn * 64];
__device__ float g_deg_s[NSn];
__device__ float g_dinv_s[NSn];

// ------------------------------- helpers -----------------------------------
__device__ __forceinline__ void red4(float* p, float a, float b, float c, float d) {
    asm volatile("red.global.add.v4.f32 [%0], {%1,%2,%3,%4};"
                 :: "l"(p), "f"(a), "f"(b), "f"(c), "f"(d) : "memory");
}
__device__ __forceinline__ void red4v(float* p, float4 v) { red4(p, v.x, v.y, v.z, v.w); }

// ------------------------------- kernels -----------------------------------

__global__ void k_pad_x(const float* __restrict__ x) {
    int t = blockIdx.x * blockDim.x + threadIdx.x;
    if (t >= NVn * 8) return;
    int v = t >> 3, i = t & 7;
    g_xpad[t] = (i < 5) ? x[v * 5 + i] : 0.f;
}

// Wz (40x64) and c0 (64)
__global__ void k_prep1(const float* __restrict__ W1_rel, const float* __restrict__ W1_root,
                        const float* __restrict__ b1,
                        const float* __restrict__ W12, const float* __restrict__ b12) {
    int t = blockIdx.x * blockDim.x + threadIdx.x;
    if (t < 64) g_c0[t] = b1[t] + b12[t];
    if (t >= 40 * 64) return;
    int i = t >> 6, c = t & 63;
    float w = 0.f;
    if (i < 5)        w = W1_root[i * 64 + c] + W12[i * 64 + c];
    else if (i < 20)  w = W1_rel[(i - 5) * 64 + c];
    else if (i < 35)  w = W12[(i - 15) * 64 + c];   // W12[k=1+(i-20)/5][j]
    g_Wz[t] = w;
}

// Products WzW[m] = Wz @ Wm, c0W[m] = c0 @ Wm
__global__ void k_prep2(const float* __restrict__ W3_rel, const float* __restrict__ W32_l,
                        const float* __restrict__ W4_l,  const float* __restrict__ W42_l) {
    int t = blockIdx.x * blockDim.x + threadIdx.x;
    if (t >= 4 * 41 * 64) return;
    int m = t / (41 * 64);
    int r = t % (41 * 64);
    int i = r >> 6, c = r & 63;
    const float* Wm = (m == 0) ? W3_rel : (m == 1) ? W32_l : (m == 2) ? W4_l : W42_l;
    float acc = 0.f;
    if (i < 40) {
        const float* zr = g_Wz + i * 64;
#pragma unroll 8
        for (int j = 0; j < 64; j++) acc += zr[j] * Wm[j * 64 + c];
        g_WzW[m][i * 64 + c] = acc;
    } else {
#pragma unroll 8
        for (int j = 0; j < 64; j++) acc += g_c0[j] * Wm[j * 64 + c];
        g_c0W[m][c] = acc;
    }
}

// RGCN edge pass: per-(dst,rel) 5-dim sums (padded 8) + counts.
__global__ void k_rgcn_edge(const int* __restrict__ ei, const int* __restrict__ et, int E) {
    int e = blockIdx.x * blockDim.x + threadIdx.x;
    if (e >= E) return;
    int s = ei[e], d = ei[E + e], t = et[e];
    const float4* xs = (const float4*)(g_xpad + (size_t)s * 8);
    float4 a = xs[0], b = xs[1];
    float* p = g_racc + (size_t)d * 24 + t * 8;
    red4v(p, a);
    red4(p + 4, b.x, 0.f, 0.f, 0.f);
    atomicAdd(g_rcnt + d * 4 + t, 1.f);
}

__global__ void k_dinv_v() {
    int v = blockIdx.x * blockDim.x + threadIdx.x;
    if (v >= NVn) return;
    float deg = g_rcnt[v * 4] + g_rcnt[v * 4 + 1] + g_rcnt[v * 4 + 2];
    g_dinv_v[v] = (deg > 0.f) ? rsqrtf(deg) : 0.f;
}

// TAG-game hop: 8-float (padded) normalized scatter, thread per edge.
__global__ void k_hop8(const float* __restrict__ hp, float* __restrict__ hn,
                       const int* __restrict__ ei, int E) {
    int e = blockIdx.x * blockDim.x + threadIdx.x;
    if (e >= E) return;
    int s = ei[e], d = ei[E + e];
    float nrm = g_dinv_v[s] * g_dinv_v[d];
    if (nrm == 0.f) return;
    const float4* hs = (const float4*)(hp + (size_t)s * 8);
    float4 a = hs[0], b = hs[1];
    float* p = hn + (size_t)d * 8;
    red4(p,     nrm * a.x, nrm * a.y, nrm * a.z, nrm * a.w);
    red4(p + 4, nrm * b.x, 0.f, 0.f, 0.f);
}

// Build z[v][40] = [x(5), racc_norm(15), hv(15), 0(5)]
__global__ void k_build_z() {
    int t = blockIdx.x * blockDim.x + threadIdx.x;
    if (t >= NVn * 40) return;
    int v = t / 40, i = t - v * 40;
    float val = 0.f;
    if (i < 5) {
        val = g_xpad[v * 8 + i];
    } else if (i < 20) {
        int r = (i - 5) / 5, j = (i - 5) - r * 5;
        val = g_racc[(size_t)v * 24 + r * 8 + j] / fmaxf(g_rcnt[v * 4 + r], 1.f);
    } else if (i < 35) {
        int k = (i - 20) / 5, j = (i - 20) - k * 5;
        val = g_hv[k][(size_t)v * 8 + j];
    }
    g_z[(size_t)v * 40 + i] = val;
}

// ei_h fused: weighted z-sum + plain z-sum + count + weight-sum. 2 edges/warp.
__global__ void k_scatter_h(const int* __restrict__ ei, const float* __restrict__ ew, int E) {
    int gt = blockIdx.x * blockDim.x + threadIdx.x;
    int warp = gt >> 5, lane = gt & 31;
    int sub = lane >> 4, li = lane & 15;
    int e = warp * 2 + sub;
    if (e >= E) return;
    int s = 0, d = 0; float wt = 0.f;
    if (li == 0) { s = ei[e]; d = ei[E + e]; wt = ew[e]; }
    s  = __shfl_sync(0xffffffffu, s, 0, 16);
    d  = __shfl_sync(0xffffffffu, d, 0, 16);
    wt = __shfl_sync(0xffffffffu, wt, 0, 16);
    if (li < 10) {
        float4 v = ((const float4*)(g_z + (size_t)s * 40))[li];
        float* pw = g_aggw + (size_t)d * 40 + li * 4;
        float* pu = g_aggu + (size_t)d * 40 + li * 4;
        red4(pw, wt * v.x, wt * v.y, wt * v.z, wt * v.w);
        red4v(pu, v);
    } else if (li == 10) {
        atomicAdd(g_cnt_h + d, 1.f);
    } else if (li == 11) {
        atomicAdd(g_wsum_h + d, wt);
    }
}

// ei_in z-sum + count. 2 edges/warp.
__global__ void k_scatter_in(const int* __restrict__ ei, int E) {
    int gt = blockIdx.x * blockDim.x + threadIdx.x;
    int warp = gt >> 5, lane = gt & 31;
    int sub = lane >> 4, li = lane & 15;
    int e = warp * 2 + sub;
    if (e >= E) return;
    int s = 0, d = 0;
    if (li == 0) { s = ei[e]; d = ei[E + e]; }
    s = __shfl_sync(0xffffffffu, s, 0, 16);
    d = __shfl_sync(0xffffffffu, d, 0, 16);
    if (li < 10) {
        float4 v = ((const float4*)(g_z + (size_t)s * 40))[li];
        red4v(g_aggin + (size_t)d * 40 + li * 4, v);
    } else if (li == 10) {
        atomicAdd(g_cnt_in + d, 1.f);
    }
}

// graph_conv: relu( aggw@WzW3 + wsum*c0W3 + state_x@W3_root + b3 )
__global__ void k_dense_gc(const float* __restrict__ state_x, const float* __restrict__ W3_root,
                           const float* __restrict__ b3, float* __restrict__ out) {
    int t = blockIdx.x * blockDim.x + threadIdx.x;
    int v = t >> 6, c = t & 63;
    if (v >= NSn) return;
    const float* a = g_aggw + (size_t)v * 40;
    const float* W = g_WzW[0];
    float acc = b3[c] + g_wsum_h[v] * g_c0W[0][c];
#pragma unroll 5
    for (int i = 0; i < 35; i++) acc += a[i] * W[i * 64 + c];
    const float* xv = state_x + (size_t)v * 5;
#pragma unroll
    for (int j = 0; j < 5; j++) acc += xv[j] * W3_root[j * 64 + c];
    out[(size_t)v * 64 + c] = fmaxf(acc, 0.f);
}

// SAGE in z-space: relu( (aggz/cnt)@WzW[m] + [cnt>0]*c0W[m] + Xprev@Wr + b )
__global__ void k_dense_mean40(const float* __restrict__ aggz, const float* __restrict__ cnt,
                               int m, const float* __restrict__ Xprev,
                               const float* __restrict__ Wr, const float* __restrict__ b,
                               float* __restrict__ out) {
    int t = blockIdx.x * blockDim.x + threadIdx.x;
    int v = t >> 6, c = t & 63;
    if (v >= NSn) return;
    float cv = cnt[v];
    float inv = 1.f / fmaxf(cv, 1.f);
    const float* a = aggz + (size_t)v * 40;
    const float* W = g_WzW[m];
    float sa = 0.f;
#pragma unroll 5
    for (int i = 0; i < 35; i++) sa += a[i] * W[i * 64 + c];
    float acc = b[c] + sa * inv + ((cv > 0.f) ? g_c0W[m][c] : 0.f);
    const float* xv = Xprev + (size_t)v * 64;
#pragma unroll 8
    for (int j = 0; j < 64; j++) acc += xv[j] * Wr[j * 64 + c];
    out[(size_t)v * 64 + c] = fmaxf(acc, 0.f);
}

__global__ void k_count(const int* __restrict__ ei, float* __restrict__ cnt, int E) {
    int e = blockIdx.x * blockDim.x + threadIdx.x;
    if (e >= E) return;
    atomicAdd(cnt + ei[E + e], 1.f);
}

__global__ void k_dinv_s() {
    int v = blockIdx.x * blockDim.x + threadIdx.x;
    if (v >= NSn) return;
    float d = g_deg_s[v];
    g_dinv_s[v] = (d > 0.f) ? rsqrtf(d) : 0.f;
}

// TAG-state hop: 64-dim normalized scatter, 2 edges/warp, v4 atomics.
__global__ void k_hop64(const int* __restrict__ ei, const float* __restrict__ hp,
                        float* __restrict__ hn, int E) {
    int gt = blockIdx.x * blockDim.x + threadIdx.x;
    int warp = gt >> 5, lane = gt & 31;
    int sub = lane >> 4, li = lane & 15;
    int e = warp * 2 + sub;
    if (e >= E) return;
    int s = 0, d = 0;
    if (li == 0) { s = ei[e]; d = ei[E + e]; }
    s = __shfl_sync(0xffffffffu, s, 0, 16);
    d = __shfl_sync(0xffffffffu, d, 0, 16);
    float nrm = g_dinv_s[s] * g_dinv_s[d];
    if (nrm == 0.f) return;
    float4 v = ((const float4*)(hp + (size_t)s * 64))[li];
    red4(hn + (size_t)d * 64 + li * 4, nrm * v.x, nrm * v.y, nrm * v.z, nrm * v.w);
}

// 64-dim sum scatter (conv5), 2 edges/warp.
__global__ void k_scatter64(const int* __restrict__ ei, const float* __restrict__ feat,
                            float* __restrict__ acc, int E) {
    int gt = blockIdx.x * blockDim.x + threadIdx.x;
    int warp = gt >> 5, lane = gt & 31;
    int sub = lane >> 4, li = lane & 15;
    int e = warp * 2 + sub;
    if (e >= E) return;
    int s = 0, d = 0;
    if (li == 0) { s = ei[e]; d = ei[E + e]; }
    s = __shfl_sync(0xffffffffu, s, 0, 16);
    d = __shfl_sync(0xffffffffu, d, 0, 16);
    float4 v = ((const float4*)(feat + (size_t)s * 64))[li];
    red4v(acc + (size_t)d * 64 + li * 4, v);
}

// TAG-state out: relu(b2 + sx@W2[0] + sum_k hs_k@W2[k+1])
__global__ void k_tag_out(const float* __restrict__ sx, const float* __restrict__ W2,
                          const float* __restrict__ b2, float* __restrict__ out) {
    int t = blockIdx.x * blockDim.x + threadIdx.x;
    int v = t >> 6, c = t & 63;
    if (v >= NSn) return;
    float acc = b2[c];
    const float* s0 = sx + (size_t)v * 64;
#pragma unroll 8
    for (int j = 0; j < 64; j++) acc += s0[j] * W2[j * 64 + c];
#pragma unroll
    for (int k = 0; k < 3; k++) {
        const float* hk = g_hs[k] + (size_t)v * 64;
        const float* wk = W2 + (size_t)(k + 1) * 4096;
#pragma unroll 8
        for (int j = 0; j < 64; j++) acc += hk[j] * wk[j * 64 + c];
    }
    out[(size_t)v * 64 + c] = fmaxf(acc, 0.f);
}

// conv5 SAGE (64-dim agg): relu( (acc/deg)@W5_l + sx@W5_r + b5 )
__global__ void k_dense64(const float* __restrict__ A, const float* __restrict__ cnt,
                          const float* __restrict__ Wa, const float* __restrict__ X,
                          const float* __restrict__ Wx, const float* __restrict__ b,
                          float* __restrict__ out) {
    int t = blockIdx.x * blockDim.x + threadIdx.x;
    int v = t >> 6, c = t & 63;
    if (v >= NSn) return;
    float inv = 1.f / fmaxf(cnt[v], 1.f);
    const float* av = A + (size_t)v * 64;
    float sa = 0.f;
#pragma unroll 8
    for (int j = 0; j < 64; j++) sa += av[j] * Wa[j * 64 + c];
    float acc = b[c] + sa * inv;
    const float* xv = X + (size_t)v * 64;
#pragma unroll 8
    for (int j = 0; j < 64; j++) acc += xv[j] * Wx[j * 64 + c];
    out[(size_t)v * 64 + c] = fmaxf(acc, 0.f);
}

__global__ void k_final(const float* __restrict__ sx, const float* __restrict__ Wl,
                        const float* __restrict__ bl, float* __restrict__ out) {
    int t = blockIdx.x * blockDim.x + threadIdx.x;
    int v = t >> 3, c = t & 7;
    if (v >= NSn) return;
    float acc = bl[c];
    const float* s0 = sx + (size_t)v * 64;
#pragma unroll 8
    for (int j = 0; j < 64; j++) acc += s0[j] * Wl[j * 8 + c];
    out[(size_t)v * 8 + c] = acc;
}

// ------------------------------- launch ------------------------------------

extern "C" void kernel_launch(void* const* d_in, const int* in_sizes, int n_in,
                              void* d_out, int out_size) {
    const float* game_x  = (const float*)d_in[0];
    const float* state_x = (const float*)d_in[1];
    const int*   ei_vv   = (const int*)d_in[2];
    const int*   et_vv   = (const int*)d_in[3];
    const int*   ei_h    = (const int*)d_in[4];
    const float* ew_h    = (const float*)d_in[5];
    const int*   ei_in   = (const int*)d_in[6];
    const int*   ei_ss   = (const int*)d_in[7];
    const float* W1_rel  = (const float*)d_in[8];
    const float* W1_root = (const float*)d_in[9];
    const float* b1      = (const float*)d_in[10];
    const float* W12     = (const float*)d_in[11];
    const float* b12     = (const float*)d_in[12];
    const float* W2      = (const float*)d_in[13];
    const float* b2      = (const float*)d_in[14];
    const float* W3_rel  = (const float*)d_in[15];
    const float* W3_root = (const float*)d_in[16];
    const float* b3      = (const float*)d_in[17];
    const float* W32_l   = (const float*)d_in[18];
    const float* W32_r   = (const float*)d_in[19];
    const float* b32     = (const float*)d_in[20];
    const float* W4_l    = (const float*)d_in[21];
    const float* W4_r    = (const float*)d_in[22];
    const float* b4      = (const float*)d_in[23];
    const float* W42_l   = (const float*)d_in[24];
    const float* W42_r   = (const float*)d_in[25];
    const float* b42     = (const float*)d_in[26];
    const float* W5_l    = (const float*)d_in[27];
    const float* W5_r    = (const float*)d_in[28];
    const float* b5      = (const float*)d_in[29];
    const float* Wl      = (const float*)d_in[30];
    const float* bl      = (const float*)d_in[31];
    float* out = (float*)d_out;

    int Evv = in_sizes[2] / 2;
    int Eh  = in_sizes[4] / 2;
    int Ein = in_sizes[6] / 2;
    int Ess = in_sizes[7] / 2;

    // scratch addresses for memsets / ping-pong params
    float *p_racc, *p_rcnt, *p_hv, *p_aggw, *p_aggu, *p_cnt_h, *p_wsum_h;
    float *p_aggin, *p_cnt_in, *p_hs, *p_accs5, *p_deg_s, *p_xpad, *p_sxA, *p_sxB;
    cudaGetSymbolAddress((void**)&p_racc,   g_racc);
    cudaGetSymbolAddress((void**)&p_rcnt,   g_rcnt);
    cudaGetSymbolAddress((void**)&p_hv,     g_hv);
    cudaGetSymbolAddress((void**)&p_aggw,   g_aggw);
    cudaGetSymbolAddress((void**)&p_aggu,   g_aggu);
    cudaGetSymbolAddress((void**)&p_cnt_h,  g_cnt_h);
    cudaGetSymbolAddress((void**)&p_wsum_h, g_wsum_h);
    cudaGetSymbolAddress((void**)&p_aggin,  g_aggin);
    cudaGetSymbolAddress((void**)&p_cnt_in, g_cnt_in);
    cudaGetSymbolAddress((void**)&p_hs,     g_hs);
    cudaGetSymbolAddress((void**)&p_accs5,  g_accs5);
    cudaGetSymbolAddress((void**)&p_deg_s,  g_deg_s);
    cudaGetSymbolAddress((void**)&p_xpad,   g_xpad);
    cudaGetSymbolAddress((void**)&p_sxA,    g_sxA);
    cudaGetSymbolAddress((void**)&p_sxB,    g_sxB);
    float* p_hv0 = p_hv;
    float* p_hv1 = p_hv + (size_t)NVn * 8;
    float* p_hv2 = p_hv1 + (size_t)NVn * 8;
    float* p_hs0 = p_hs;
    float* p_hs1 = p_hs + (size_t)NSn * 64;
    float* p_hs2 = p_hs1 + (size_t)NSn * 64;

    const int T = 256;
    auto nb = [](long n, int t) { return (int)((n + t - 1) / t); };
    auto wb = [](long edges, int t) {  // blocks for 2-edge/warp kernels
        long warps = (edges + 1) / 2;
        return (int)((warps * 32 + t - 1) / t);
    };

    // 0) zero accumulators
    cudaMemsetAsync(p_racc,   0, (size_t)NVn * 24 * 4, 0);
    cudaMemsetAsync(p_rcnt,   0, (size_t)NVn * 4 * 4, 0);
    cudaMemsetAsync(p_hv,     0, (size_t)NVn * 8 * 3 * 4, 0);
    cudaMemsetAsync(p_aggw,   0, (size_t)NSn * 40 * 4, 0);
    cudaMemsetAsync(p_aggu,   0, (size_t)NSn * 40 * 4, 0);
    cudaMemsetAsync(p_cnt_h,  0, (size_t)NSn * 4, 0);
    cudaMemsetAsync(p_wsum_h, 0, (size_t)NSn * 4, 0);
    cudaMemsetAsync(p_aggin,  0, (size_t)NSn * 40 * 4, 0);
    cudaMemsetAsync(p_cnt_in, 0, (size_t)NSn * 4, 0);
    cudaMemsetAsync(p_hs,     0, (size_t)NSn * 64 * 3 * 4, 0);
    cudaMemsetAsync(p_accs5,  0, (size_t)NSn * 64 * 4, 0);
    cudaMemsetAsync(p_deg_s,  0, (size_t)NSn * 4, 0);

    // 1) prep
    k_pad_x<<<nb((long)NVn * 8, T), T>>>(game_x);
    k_prep1<<<nb(40 * 64, T), T>>>(W1_rel, W1_root, b1, W12, b12);
    k_prep2<<<nb(4 * 41 * 64, T), T>>>(W3_rel, W32_l, W4_l, W42_l);

    // 2) game graph
    k_rgcn_edge<<<nb(Evv, T), T>>>(ei_vv, et_vv, Evv);
    k_dinv_v<<<nb(NVn, T), T>>>();
    k_hop8<<<nb(Evv, T), T>>>(p_xpad, p_hv0, ei_vv, Evv);
    k_hop8<<<nb(Evv, T), T>>>(p_hv0, p_hv1, ei_vv, Evv);
    k_hop8<<<nb(Evv, T), T>>>(p_hv1, p_hv2, ei_vv, Evv);
    k_build_z<<<nb((long)NVn * 40, T), T>>>();

    // 3) v->s aggregations in z-space
    k_scatter_h<<<wb(Eh, T), T>>>(ei_h, ew_h, Eh);
    k_scatter_in<<<wb(Ein, T), T>>>(ei_in, Ein);

    // 4) state dense chain
    k_dense_gc<<<nb((long)NSn * 64, T), T>>>(state_x, W3_root, b3, p_sxA);
    k_dense_mean40<<<nb((long)NSn * 64, T), T>>>(p_aggu, p_cnt_h, 1, p_sxA, W32_r, b32, p_sxB);
    k_dense_mean40<<<nb((long)NSn * 64, T), T>>>(p_aggin, p_cnt_in, 2, p_sxB, W4_r, b4, p_sxA);
    k_dense_mean40<<<nb((long)NSn * 64, T), T>>>(p_aggin, p_cnt_in, 3, p_sxA, W42_r, b42, p_sxB);

    // 5) TAG-state over ei_ss (input sx5 = sxB)
    k_count<<<nb(Ess, T), T>>>(ei_ss, p_deg_s, Ess);
    k_dinv_s<<<nb(NSn, T), T>>>();
    k_hop64<<<wb(Ess, T), T>>>(ei_ss, p_sxB, p_hs0, Ess);
    k_hop64<<<wb(Ess, T), T>>>(ei_ss, p_hs0, p_hs1, Ess);
    k_hop64<<<wb(Ess, T), T>>>(ei_ss, p_hs1, p_hs2, Ess);
    k_tag_out<<<nb((long)NSn * 64, T), T>>>(p_sxB, W2, b2, p_sxA);   // sx6 = sxA

    // 6) conv5 SAGE over ei_ss (count = deg_s)
    k_scatter64<<<wb(Ess, T), T>>>(ei_ss, p_sxA, p_accs5, Ess);
    k_dense64<<<nb((long)NSn * 64, T), T>>>(p_accs5, p_deg_s, W5_l, p_sxA, W5_r, b5, p_sxB);

    // 7) head
    k_final<<<nb((long)NSn * 8, T), T>>>(p_sxB, Wl, bl, out);
}

// round 3
// speedup vs baseline: 1.5681x; 1.1066x over previous
#include <cuda_runtime.h>
#include <math.h>

// ---------------------------------------------------------------------------
// StateModelEncoder — round 3: CSR-gather for reused edge sets (ei_vv, ei_ss),
// pre-scaled hop features, z-space aggregation retained for v->s scatters.
// ---------------------------------------------------------------------------

#define NVn 100000
#define NSn 50000
#define EVVmax 1600000
#define ESSmax 800000

// ------------------------- scratch (device globals) ------------------------
__device__ __align__(16) float g_xpad[NVn * 8];
__device__ __align__(16) float g_pv[2][NVn * 8];       // prescaled hop ping-pong (game)
__device__ __align__(16) float g_z[NVn * 40];
__device__ __align__(16) float g_Wz[40 * 64];
__device__ float g_c0[64];
__device__ __align__(16) float g_WzW[4][40 * 64];
__device__ float g_c0W[4][64];
__device__ __align__(16) float g_aggw[NSn * 40];
__device__ __align__(16) float g_aggu[NSn * 40];
__device__ float g_cnt_h[NSn];
__device__ float g_wsum_h[NSn];
__device__ __align__(16) float g_aggin[NSn * 40];
__device__ float g_cnt_in[NSn];
__device__ __align__(16) float g_sxA[NSn * 64];
__device__ __align__(16) float g_sxB[NSn * 64];
__device__ __align__(16) float g_hs[3][NSn * 64];
__device__ __align__(16) float g_ps[2][NSn * 64];      // prescaled hop ping-pong (state)
__device__ __align__(16) float g_accs5[NSn * 64];
__device__ float g_dinv_v[NVn];
__device__ float g_dinv_s[NSn];
__device__ float g_cntf_s[NSn];

// CSR structures
__device__ int g_deg_vv[NVn];
__device__ int g_off_vv[NVn];
__device__ int g_cur_vv[NVn];
__device__ int g_tmp_vv[NVn];
__device__ int g_part_vv[128];
__device__ int g_csr_vv[EVVmax];       // packed: src | (etype<<20)
__device__ int g_deg_ss[NSn];
__device__ int g_off_ss[NSn];
__device__ int g_cur_ss[NSn];
__device__ int g_tmp_ss[NSn];
__device__ int g_part_ss[128];
__device__ int g_csr_ss[ESSmax];

// ------------------------------- helpers -----------------------------------
__device__ __forceinline__ void red4(float* p, float a, float b, float c, float d) {
    asm volatile("red.global.add.v4.f32 [%0], {%1,%2,%3,%4};"
                 :: "l"(p), "f"(a), "f"(b), "f"(c), "f"(d) : "memory");
}
__device__ __forceinline__ void red4v(float* p, float4 v) { red4(p, v.x, v.y, v.z, v.w); }

// ------------------------------ CSR build ----------------------------------
__global__ void k_count_i(const int* __restrict__ ei, int* __restrict__ deg, int E) {
    int e = blockIdx.x * blockDim.x + threadIdx.x;
    if (e >= E) return;
    atomicAdd(deg + ei[E + e], 1);
}

__global__ void k_scan1(const int* __restrict__ deg, int* __restrict__ incl,
                        int* __restrict__ part, int n) {
    __shared__ int sh[1024];
    int i = blockIdx.x * 1024 + threadIdx.x;
    int v = (i < n) ? deg[i] : 0;
    sh[threadIdx.x] = v;
    __syncthreads();
    for (int o = 1; o < 1024; o <<= 1) {
        int t = (threadIdx.x >= o) ? sh[threadIdx.x - o] : 0;
        __syncthreads();
        sh[threadIdx.x] += t;
        __syncthreads();
    }
    if (i < n) incl[i] = sh[threadIdx.x];
    if (threadIdx.x == 1023) part[blockIdx.x] = sh[1023];
}

__global__ void k_scan2(int* __restrict__ part, int nb) {
    __shared__ int sh[128];
    int v = (threadIdx.x < nb) ? part[threadIdx.x] : 0;
    sh[threadIdx.x] = v;
    __syncthreads();
    for (int o = 1; o < 128; o <<= 1) {
        int t = (threadIdx.x >= o) ? sh[threadIdx.x - o] : 0;
        __syncthreads();
        sh[threadIdx.x] += t;
        __syncthreads();
    }
    if (threadIdx.x < nb) part[threadIdx.x] = sh[threadIdx.x] - v;  // exclusive
}

__global__ void k_scan3(const int* __restrict__ deg, const int* __restrict__ incl,
                        const int* __restrict__ part, int* __restrict__ off,
                        int* __restrict__ cur, int n) {
    int i = blockIdx.x * blockDim.x + threadIdx.x;
    if (i >= n) return;
    int o = incl[i] - deg[i] + part[i >> 10];
    off[i] = o;
    cur[i] = o;
}

__global__ void k_fill_vv(const int* __restrict__ ei, const int* __restrict__ et, int E) {
    int e = blockIdx.x * blockDim.x + threadIdx.x;
    if (e >= E) return;
    int s = ei[e], d = ei[E + e], t = et[e];
    int slot = atomicAdd(g_cur_vv + d, 1);
    g_csr_vv[slot] = s | (t << 20);
}

__global__ void k_fill_ss(const int* __restrict__ ei, int E) {
    int e = blockIdx.x * blockDim.x + threadIdx.x;
    if (e >= E) return;
    int s = ei[e], d = ei[E + e];
    int slot = atomicAdd(g_cur_ss + d, 1);
    g_csr_ss[slot] = s;
}

__global__ void k_dinv_v() {
    int v = blockIdx.x * blockDim.x + threadIdx.x;
    if (v >= NVn) return;
    int d = g_deg_vv[v];
    g_dinv_v[v] = (d > 0) ? rsqrtf((float)d) : 0.f;
}

__global__ void k_dinv_s() {
    int v = blockIdx.x * blockDim.x + threadIdx.x;
    if (v >= NSn) return;
    int d = g_deg_ss[v];
    g_dinv_s[v] = (d > 0) ? rsqrtf((float)d) : 0.f;
    g_cntf_s[v] = (float)d;
}

// ------------------------------ weight prep --------------------------------
__global__ void k_prep1(const float* __restrict__ W1_rel, const float* __restrict__ W1_root,
                        const float* __restrict__ b1,
                        const float* __restrict__ W12, const float* __restrict__ b12) {
    int t = blockIdx.x * blockDim.x + threadIdx.x;
    if (t < 64) g_c0[t] = b1[t] + b12[t];
    if (t >= 40 * 64) return;
    int i = t >> 6, c = t & 63;
    float w = 0.f;
    if (i < 5)        w = W1_root[i * 64 + c] + W12[i * 64 + c];
    else if (i < 20)  w = W1_rel[(i - 5) * 64 + c];
    else if (i < 35)  w = W12[(i - 15) * 64 + c];
    g_Wz[t] = w;
}

__global__ void k_prep2(const float* __restrict__ W3_rel, const float* __restrict__ W32_l,
                        const float* __restrict__ W4_l,  const float* __restrict__ W42_l) {
    int t = blockIdx.x * blockDim.x + threadIdx.x;
    if (t >= 4 * 41 * 64) return;
    int m = t / (41 * 64);
    int r = t % (41 * 64);
    int i = r >> 6, c = r & 63;
    const float* Wm = (m == 0) ? W3_rel : (m == 1) ? W32_l : (m == 2) ? W4_l : W42_l;
    float acc = 0.f;
    if (i < 40) {
        const float* zr = g_Wz + i * 64;
#pragma unroll 8
        for (int j = 0; j < 64; j++) acc += zr[j] * Wm[j * 64 + c];
        g_WzW[m][i * 64 + c] = acc;
    } else {
#pragma unroll 8
        for (int j = 0; j < 64; j++) acc += g_c0[j] * Wm[j * 64 + c];
        g_c0W[m][c] = acc;
    }
}

// --------------------------- game-graph kernels ----------------------------
// pad x, prescale p0 = dinv*x, write z[0..5)
__global__ void k_pad(const float* __restrict__ x) {
    int t = blockIdx.x * blockDim.x + threadIdx.x;
    if (t >= NVn * 8) return;
    int v = t >> 3, i = t & 7;
    float xv = (i < 5) ? x[v * 5 + i] : 0.f;
    g_xpad[t] = xv;
    g_pv[0][t] = g_dinv_v[v] * xv;
    if (i < 5) g_z[(size_t)v * 40 + i] = xv;
}

// RGCN per-rel mean via CSR gather: writes z[5..20).
// warp per dst, 8-lane subgroup per edge (4 edges in flight).
__global__ void k_rgcn_gather() {
    int gt = blockIdx.x * blockDim.x + threadIdx.x;
    int w = gt >> 5, lane = gt & 31;
    if (w >= NVn) return;
    int base = g_off_vv[w], deg = g_deg_vv[w];
    int sub = lane >> 3, li = lane & 7;
    float a0 = 0.f, a1 = 0.f, a2 = 0.f;
    float c0 = 0.f, c1 = 0.f, c2 = 0.f;
    for (int j = sub; j < deg; j += 4) {
        int pk = g_csr_vv[base + j];
        int s = pk & 0xFFFFF, t = pk >> 20;
        float xv = g_xpad[(size_t)s * 8 + li];
        if (t == 0)      { a0 += xv; c0 += 1.f; }
        else if (t == 1) { a1 += xv; c1 += 1.f; }
        else             { a2 += xv; c2 += 1.f; }
    }
#pragma unroll
    for (int o = 8; o < 32; o <<= 1) {
        a0 += __shfl_xor_sync(0xffffffffu, a0, o);
        a1 += __shfl_xor_sync(0xffffffffu, a1, o);
        a2 += __shfl_xor_sync(0xffffffffu, a2, o);
        c0 += __shfl_xor_sync(0xffffffffu, c0, o);
        c1 += __shfl_xor_sync(0xffffffffu, c1, o);
        c2 += __shfl_xor_sync(0xffffffffu, c2, o);
    }
    if (sub == 0 && li < 5) {
        float* zz = g_z + (size_t)w * 40 + 5;
        zz[li]      = a0 / fmaxf(c0, 1.f);
        zz[5 + li]  = a1 / fmaxf(c1, 1.f);
        zz[10 + li] = a2 / fmaxf(c2, 1.f);
    }
}

// TAG-game hop via CSR gather: h = dinv_d * sum(p_prev[src]); write z slice & p_next.
__global__ void k_hop8_gather(const float* __restrict__ pprev, float* __restrict__ pnext,
                              int k, int write_p) {
    int gt = blockIdx.x * blockDim.x + threadIdx.x;
    int w = gt >> 5, lane = gt & 31;
    if (w >= NVn) return;
    int base = g_off_vv[w], deg = g_deg_vv[w];
    int sub = lane >> 3, li = lane & 7;
    float acc = 0.f;
    for (int j = sub; j < deg; j += 4) {
        int s = g_csr_vv[base + j] & 0xFFFFF;
        acc += pprev[(size_t)s * 8 + li];
    }
#pragma unroll
    for (int o = 8; o < 32; o <<= 1)
        acc += __shfl_xor_sync(0xffffffffu, acc, o);
    if (sub == 0) {
        float dv = g_dinv_v[w];
        float h = dv * acc;
        if (li < 5) g_z[(size_t)w * 40 + 20 + k * 5 + li] = h;
        if (write_p) pnext[(size_t)w * 8 + li] = dv * h;
    }
}

// --------------------------- v->s atomic scatters --------------------------
__global__ void k_scatter_h(const int* __restrict__ ei, const float* __restrict__ ew, int E) {
    int gt = blockIdx.x * blockDim.x + threadIdx.x;
    int warp = gt >> 5, lane = gt & 31;
    int sub = lane >> 4, li = lane & 15;
    int e = warp * 2 + sub;
    if (e >= E) return;
    int s = 0, d = 0; float wt = 0.f;
    if (li == 0) { s = ei[e]; d = ei[E + e]; wt = ew[e]; }
    s  = __shfl_sync(0xffffffffu, s, 0, 16);
    d  = __shfl_sync(0xffffffffu, d, 0, 16);
    wt = __shfl_sync(0xffffffffu, wt, 0, 16);
    if (li < 10) {
        float4 v = ((const float4*)(g_z + (size_t)s * 40))[li];
        float* pw = g_aggw + (size_t)d * 40 + li * 4;
        float* pu = g_aggu + (size_t)d * 40 + li * 4;
        red4(pw, wt * v.x, wt * v.y, wt * v.z, wt * v.w);
        red4v(pu, v);
    } else if (li == 10) {
        atomicAdd(g_cnt_h + d, 1.f);
    } else if (li == 11) {
        atomicAdd(g_wsum_h + d, wt);
    }
}

__global__ void k_scatter_in(const int* __restrict__ ei, int E) {
    int gt = blockIdx.x * blockDim.x + threadIdx.x;
    int warp = gt >> 5, lane = gt & 31;
    int sub = lane >> 4, li = lane & 15;
    int e = warp * 2 + sub;
    if (e >= E) return;
    int s = 0, d = 0;
    if (li == 0) { s = ei[e]; d = ei[E + e]; }
    s = __shfl_sync(0xffffffffu, s, 0, 16);
    d = __shfl_sync(0xffffffffu, d, 0, 16);
    if (li < 10) {
        float4 v = ((const float4*)(g_z + (size_t)s * 40))[li];
        red4v(g_aggin + (size_t)d * 40 + li * 4, v);
    } else if (li == 10) {
        atomicAdd(g_cnt_in + d, 1.f);
    }
}

// ------------------------------ dense chain --------------------------------
__global__ void k_dense_gc(const float* __restrict__ state_x, const float* __restrict__ W3_root,
                           const float* __restrict__ b3, float* __restrict__ out) {
    int t = blockIdx.x * blockDim.x + threadIdx.x;
    int v = t >> 6, c = t & 63;
    if (v >= NSn) return;
    const float* a = g_aggw + (size_t)v * 40;
    const float* W = g_WzW[0];
    float acc = b3[c] + g_wsum_h[v] * g_c0W[0][c];
#pragma unroll 5
    for (int i = 0; i < 35; i++) acc += a[i] * W[i * 64 + c];
    const float* xv = state_x + (size_t)v * 5;
#pragma unroll
    for (int j = 0; j < 5; j++) acc += xv[j] * W3_root[j * 64 + c];
    out[(size_t)v * 64 + c] = fmaxf(acc, 0.f);
}

__global__ void k_dense_mean40(const float* __restrict__ aggz, const float* __restrict__ cnt,
                               int m, const float* __restrict__ Xprev,
                               const float* __restrict__ Wr, const float* __restrict__ b,
                               float* __restrict__ out) {
    int t = blockIdx.x * blockDim.x + threadIdx.x;
    int v = t >> 6, c = t & 63;
    if (v >= NSn) return;
    float cv = cnt[v];
    float inv = 1.f / fmaxf(cv, 1.f);
    const float* a = aggz + (size_t)v * 40;
    const float* W = g_WzW[m];
    float sa = 0.f;
#pragma unroll 5
    for (int i = 0; i < 35; i++) sa += a[i] * W[i * 64 + c];
    float acc = b[c] + sa * inv + ((cv > 0.f) ? g_c0W[m][c] : 0.f);
    const float* xv = Xprev + (size_t)v * 64;
#pragma unroll 8
    for (int j = 0; j < 64; j++) acc += xv[j] * Wr[j * 64 + c];
    out[(size_t)v * 64 + c] = fmaxf(acc, 0.f);
}

__global__ void k_prescale64(const float* __restrict__ sx, float* __restrict__ p) {
    int t = blockIdx.x * blockDim.x + threadIdx.x;
    if (t >= NSn * 64) return;
    p[t] = g_dinv_s[t >> 6] * sx[t];
}

// TAG-state hop via CSR gather. warp per dst, 2 floats/lane.
__global__ void k_hop64_gather(const float* __restrict__ pprev, float* __restrict__ hout,
                               float* __restrict__ pnext, int write_p) {
    int gt = blockIdx.x * blockDim.x + threadIdx.x;
    int w = gt >> 5, lane = gt & 31;
    if (w >= NSn) return;
    int base = g_off_ss[w], deg = g_deg_ss[w];
    float a = 0.f, b = 0.f;
    for (int j = 0; j < deg; j += 32) {
        int idx = j + lane;
        int sl = (idx < deg) ? g_csr_ss[base + idx] : 0;
        int mres = deg - j; if (mres > 32) mres = 32;
        for (int jj = 0; jj < mres; jj++) {
            int s = __shfl_sync(0xffffffffu, sl, jj);
            const float* f = pprev + (size_t)s * 64;
            a += f[lane];
            b += f[lane + 32];
        }
    }
    float dv = g_dinv_s[w];
    float ha = dv * a, hb = dv * b;
    hout[(size_t)w * 64 + lane] = ha;
    hout[(size_t)w * 64 + lane + 32] = hb;
    if (write_p) {
        pnext[(size_t)w * 64 + lane] = dv * ha;
        pnext[(size_t)w * 64 + lane + 32] = dv * hb;
    }
}

// conv5 sum via CSR gather.
__global__ void k_sum64_gather(const float* __restrict__ feat, float* __restrict__ acc) {
    int gt = blockIdx.x * blockDim.x + threadIdx.x;
    int w = gt >> 5, lane = gt & 31;
    if (w >= NSn) return;
    int base = g_off_ss[w], deg = g_deg_ss[w];
    float a = 0.f, b = 0.f;
    for (int j = 0; j < deg; j += 32) {
        int idx = j + lane;
        int sl = (idx < deg) ? g_csr_ss[base + idx] : 0;
        int mres = deg - j; if (mres > 32) mres = 32;
        for (int jj = 0; jj < mres; jj++) {
            int s = __shfl_sync(0xffffffffu, sl, jj);
            const float* f = feat + (size_t)s * 64;
            a += f[lane];
            b += f[lane + 32];
        }
    }
    acc[(size_t)w * 64 + lane] = a;
    acc[(size_t)w * 64 + lane + 32] = b;
}

__global__ void k_tag_out(const float* __restrict__ sx, const float* __restrict__ W2,
                          const float* __restrict__ b2, float* __restrict__ out) {
    int t = blockIdx.x * blockDim.x + threadIdx.x;
    int v = t >> 6, c = t & 63;
    if (v >= NSn) return;
    float acc = b2[c];
    const float* s0 = sx + (size_t)v * 64;
#pragma unroll 8
    for (int j = 0; j < 64; j++) acc += s0[j] * W2[j * 64 + c];
#pragma unroll
    for (int k = 0; k < 3; k++) {
        const float* hk = g_hs[k] + (size_t)v * 64;
        const float* wk = W2 + (size_t)(k + 1) * 4096;
#pragma unroll 8
        for (int j = 0; j < 64; j++) acc += hk[j] * wk[j * 64 + c];
    }
    out[(size_t)v * 64 + c] = fmaxf(acc, 0.f);
}

__global__ void k_dense64(const float* __restrict__ A, const float* __restrict__ cnt,
                          const float* __restrict__ Wa, const float* __restrict__ X,
                          const float* __restrict__ Wx, const float* __restrict__ b,
                          float* __restrict__ out) {
    int t = blockIdx.x * blockDim.x + threadIdx.x;
    int v = t >> 6, c = t & 63;
    if (v >= NSn) return;
    float inv = 1.f / fmaxf(cnt[v], 1.f);
    const float* av = A + (size_t)v * 64;
    float sa = 0.f;
#pragma unroll 8
    for (int j = 0; j < 64; j++) sa += av[j] * Wa[j * 64 + c];
    float acc = b[c] + sa * inv;
    const float* xv = X + (size_t)v * 64;
#pragma unroll 8
    for (int j = 0; j < 64; j++) acc += xv[j] * Wx[j * 64 + c];
    out[(size_t)v * 64 + c] = fmaxf(acc, 0.f);
}

__global__ void k_final(const float* __restrict__ sx, const float* __restrict__ Wl,
                        const float* __restrict__ bl, float* __restrict__ out) {
    int t = blockIdx.x * blockDim.x + threadIdx.x;
    int v = t >> 3, c = t & 7;
    if (v >= NSn) return;
    float acc = bl[c];
    const float* s0 = sx + (size_t)v * 64;
#pragma unroll 8
    for (int j = 0; j < 64; j++) acc += s0[j] * Wl[j * 8 + c];
    out[(size_t)v * 8 + c] = acc;
}

// ------------------------------- launch ------------------------------------

extern "C" void kernel_launch(void* const* d_in, const int* in_sizes, int n_in,
                              void* d_out, int out_size) {
    const float* game_x  = (const float*)d_in[0];
    const float* state_x = (const float*)d_in[1];
    const int*   ei_vv   = (const int*)d_in[2];
    const int*   et_vv   = (const int*)d_in[3];
    const int*   ei_h    = (const int*)d_in[4];
    const float* ew_h    = (const float*)d_in[5];
    const int*   ei_in   = (const int*)d_in[6];
    const int*   ei_ss   = (const int*)d_in[7];
    const float* W1_rel  = (const float*)d_in[8];
    const float* W1_root = (const float*)d_in[9];
    const float* b1      = (const float*)d_in[10];
    const float* W12     = (const float*)d_in[11];
    const float* b12     = (const float*)d_in[12];
    const float* W2      = (const float*)d_in[13];
    const float* b2      = (const float*)d_in[14];
    const float* W3_rel  = (const float*)d_in[15];
    const float* W3_root = (const float*)d_in[16];
    const float* b3      = (const float*)d_in[17];
    const float* W32_r   = (const float*)d_in[19];
    const float* b32     = (const float*)d_in[20];
    const float* W4_r    = (const float*)d_in[22];
    const float* b4      = (const float*)d_in[23];
    const float* W42_r   = (const float*)d_in[25];
    const float* b42     = (const float*)d_in[26];
    const float* W5_l    = (const float*)d_in[27];
    const float* W5_r    = (const float*)d_in[28];
    const float* b5      = (const float*)d_in[29];
    const float* Wl      = (const float*)d_in[30];
    const float* bl      = (const float*)d_in[31];
    const float* W32_l   = (const float*)d_in[18];
    const float* W4_l    = (const float*)d_in[21];
    const float* W42_l   = (const float*)d_in[24];
    float* out = (float*)d_out;

    int Evv = in_sizes[2] / 2;
    int Eh  = in_sizes[4] / 2;
    int Ein = in_sizes[6] / 2;
    int Ess = in_sizes[7] / 2;

    // symbol addresses
    float *p_aggw, *p_aggu, *p_cnt_h, *p_wsum_h, *p_aggin, *p_cnt_in;
    float *p_sxA, *p_sxB, *p_hs, *p_ps, *p_accs5, *p_cntf_s, *p_pv, *p_z;
    int *pi_deg_vv, *pi_tmp_vv, *pi_part_vv, *pi_off_vv, *pi_cur_vv;
    int *pi_deg_ss, *pi_tmp_ss, *pi_part_ss, *pi_off_ss, *pi_cur_ss;
    cudaGetSymbolAddress((void**)&p_aggw,   g_aggw);
    cudaGetSymbolAddress((void**)&p_aggu,   g_aggu);
    cudaGetSymbolAddress((void**)&p_cnt_h,  g_cnt_h);
    cudaGetSymbolAddress((void**)&p_wsum_h, g_wsum_h);
    cudaGetSymbolAddress((void**)&p_aggin,  g_aggin);
    cudaGetSymbolAddress((void**)&p_cnt_in, g_cnt_in);
    cudaGetSymbolAddress((void**)&p_sxA,    g_sxA);
    cudaGetSymbolAddress((void**)&p_sxB,    g_sxB);
    cudaGetSymbolAddress((void**)&p_hs,     g_hs);
    cudaGetSymbolAddress((void**)&p_ps,     g_ps);
    cudaGetSymbolAddress((void**)&p_accs5,  g_accs5);
    cudaGetSymbolAddress((void**)&p_cntf_s, g_cntf_s);
    cudaGetSymbolAddress((void**)&p_pv,     g_pv);
    cudaGetSymbolAddress((void**)&p_z,      g_z);
    cudaGetSymbolAddress((void**)&pi_deg_vv, g_deg_vv);
    cudaGetSymbolAddress((void**)&pi_tmp_vv, g_tmp_vv);
    cudaGetSymbolAddress((void**)&pi_part_vv,g_part_vv);
    cudaGetSymbolAddress((void**)&pi_off_vv, g_off_vv);
    cudaGetSymbolAddress((void**)&pi_cur_vv, g_cur_vv);
    cudaGetSymbolAddress((void**)&pi_deg_ss, g_deg_ss);
    cudaGetSymbolAddress((void**)&pi_tmp_ss, g_tmp_ss);
    cudaGetSymbolAddress((void**)&pi_part_ss,g_part_ss);
    cudaGetSymbolAddress((void**)&pi_off_ss, g_off_ss);
    cudaGetSymbolAddress((void**)&pi_cur_ss, g_cur_ss);

    float* p_pv0 = p_pv;
    float* p_pv1 = p_pv + (size_t)NVn * 8;
    float* p_hs0 = p_hs;
    float* p_hs1 = p_hs + (size_t)NSn * 64;
    float* p_hs2 = p_hs1 + (size_t)NSn * 64;
    float* p_ps0 = p_ps;
    float* p_ps1 = p_ps + (size_t)NSn * 64;

    const int T = 256;
    auto nb = [](long n, int t) { return (int)((n + t - 1) / t); };
    auto wb = [](long edges, int t) {
        long warps = (edges + 1) / 2;
        return (int)((warps * 32 + t - 1) / t);
    };
    int nbv_warp = nb((long)NVn * 32, T);
    int nbs_warp = nb((long)NSn * 32, T);

    // 0) zeros
    cudaMemsetAsync(p_aggw,   0, (size_t)NSn * 40 * 4, 0);
    cudaMemsetAsync(p_aggu,   0, (size_t)NSn * 40 * 4, 0);
    cudaMemsetAsync(p_cnt_h,  0, (size_t)NSn * 4, 0);
    cudaMemsetAsync(p_wsum_h, 0, (size_t)NSn * 4, 0);
    cudaMemsetAsync(p_aggin,  0, (size_t)NSn * 40 * 4, 0);
    cudaMemsetAsync(p_cnt_in, 0, (size_t)NSn * 4, 0);
    cudaMemsetAsync(p_z,      0, (size_t)NVn * 40 * 4, 0);
    cudaMemsetAsync(pi_deg_vv, 0, (size_t)NVn * 4, 0);
    cudaMemsetAsync(pi_deg_ss, 0, (size_t)NSn * 4, 0);

    // 1) weight prep
    k_prep1<<<nb(40 * 64, T), T>>>(W1_rel, W1_root, b1, W12, b12);
    k_prep2<<<nb(4 * 41 * 64, T), T>>>(W3_rel, W32_l, W4_l, W42_l);

    // 2) CSR build (vv and ss)
    k_count_i<<<nb(Evv, T), T>>>(ei_vv, pi_deg_vv, Evv);
    k_scan1<<<nb(NVn, 1024), 1024>>>(pi_deg_vv, pi_tmp_vv, pi_part_vv, NVn);
    k_scan2<<<1, 128>>>(pi_part_vv, nb(NVn, 1024));
    k_scan3<<<nb(NVn, T), T>>>(pi_deg_vv, pi_tmp_vv, pi_part_vv, pi_off_vv, pi_cur_vv, NVn);
    k_fill_vv<<<nb(Evv, T), T>>>(ei_vv, et_vv, Evv);
    k_dinv_v<<<nb(NVn, T), T>>>();

    k_count_i<<<nb(Ess, T), T>>>(ei_ss, pi_deg_ss, Ess);
    k_scan1<<<nb(NSn, 1024), 1024>>>(pi_deg_ss, pi_tmp_ss, pi_part_ss, NSn);
    k_scan2<<<1, 128>>>(pi_part_ss, nb(NSn, 1024));
    k_scan3<<<nb(NSn, T), T>>>(pi_deg_ss, pi_tmp_ss, pi_part_ss, pi_off_ss, pi_cur_ss, NSn);
    k_fill_ss<<<nb(Ess, T), T>>>(ei_ss, Ess);
    k_dinv_s<<<nb(NSn, T), T>>>();

    // 3) game graph gathers -> z
    k_pad<<<nb((long)NVn * 8, T), T>>>(game_x);
    k_rgcn_gather<<<nbv_warp, T>>>();
    k_hop8_gather<<<nbv_warp, T>>>(p_pv0, p_pv1, 0, 1);
    k_hop8_gather<<<nbv_warp, T>>>(p_pv1, p_pv0, 1, 1);
    k_hop8_gather<<<nbv_warp, T>>>(p_pv0, p_pv1, 2, 0);

    // 4) v->s aggregations in z-space (atomic)
    k_scatter_h<<<wb(Eh, T), T>>>(ei_h, ew_h, Eh);
    k_scatter_in<<<wb(Ein, T), T>>>(ei_in, Ein);

    // 5) state dense chain
    k_dense_gc<<<nb((long)NSn * 64, T), T>>>(state_x, W3_root, b3, p_sxA);
    k_dense_mean40<<<nb((long)NSn * 64, T), T>>>(p_aggu, p_cnt_h, 1, p_sxA, W32_r, b32, p_sxB);
    k_dense_mean40<<<nb((long)NSn * 64, T), T>>>(p_aggin, p_cnt_in, 2, p_sxB, W4_r, b4, p_sxA);
    k_dense_mean40<<<nb((long)NSn * 64, T), T>>>(p_aggin, p_cnt_in, 3, p_sxA, W42_r, b42, p_sxB);

    // 6) TAG-state hops via CSR gather
    k_prescale64<<<nb((long)NSn * 64, T), T>>>(p_sxB, p_ps0);
    k_hop64_gather<<<nbs_warp, T>>>(p_ps0, p_hs0, p_ps1, 1);
    k_hop64_gather<<<nbs_warp, T>>>(p_ps1, p_hs1, p_ps0, 1);
    k_hop64_gather<<<nbs_warp, T>>>(p_ps0, p_hs2, p_ps1, 0);
    k_tag_out<<<nb((long)NSn * 64, T), T>>>(p_sxB, W2, b2, p_sxA);   // sx6 = sxA

    // 7) conv5 via CSR gather
    k_sum64_gather<<<nbs_warp, T>>>(p_sxA, p_accs5);
    k_dense64<<<nb((long)NSn * 64, T), T>>>(p_accs5, p_cntf_s, W5_l, p_sxA, W5_r, b5, p_sxB);

    // 8) head
    k_final<<<nb((long)NSn * 8, T), T>>>(p_sxB, Wl, bl, out);
}